// round 3
// baseline (speedup 1.0000x reference)
#include <cuda_runtime.h>

// Voronoi nearest-site via fine-grid candidate LUT. Reference-exact fp32:
//   a  = rn(rn(x0^2) + rn(x1^2))
//   e  = fmaf(x1, sy, rn(x0*sx))
//   d2 = rn(rn(a - 2*e) + cs),  cs = rn(rn(sx^2) + rn(sy^2))
//   argmin: ascending scan, strict <
//
// R2 -> R3: 740 CTAs (exactly 5/SM, no tail wave); 4 points/thread with
// float4 loads/stores; candidate table fused to one float4 (sx,sy,cs);
// vectorized smem staging.

#define GR 96
#define NS 100
#define NCELL (GR * GR)

__device__ unsigned int g_grid[NCELL];
__device__ float4 g_cand[NS];   // sx, sy, cs, 0
__device__ float4 g_rgb[NS];    // r, g, b, 0

__global__ void build_lut(const float* __restrict__ p) {
    __shared__ float sp[2 * NS];   // sx, sy pairs
    if (threadIdx.x < NS) {
        float sx = p[1 + 5 * threadIdx.x];
        float sy = p[2 + 5 * threadIdx.x];
        sp[2 * threadIdx.x + 0] = sx;
        sp[2 * threadIdx.x + 1] = sy;
    }
    __syncthreads();

    int cell = blockIdx.x * blockDim.x + threadIdx.x;
    if (cell < NS) {
        float sx = sp[2 * cell], sy = sp[2 * cell + 1];
        float cs = __fadd_rn(__fmul_rn(sx, sx), __fmul_rn(sy, sy));
        g_cand[cell] = make_float4(sx, sy, cs, 0.0f);
        g_rgb[cell]  = make_float4(p[3 + 5 * cell], p[4 + 5 * cell], p[5 + 5 * cell], 0.0f);
    }
    if (cell >= NCELL) return;

    int gy = cell / GR;
    int gx = cell - gy * GR;
    float cx = (gx + 0.5f) * (1.0f / GR);
    float cy = (gy + 0.5f) * (1.0f / GR);

    // Pass 1: nearest d^2 from cell center.
    float best = 3.4e38f;
    #pragma unroll 4
    for (int s = 0; s < NS; s++) {
        float dx = cx - sp[2 * s];
        float dy = cy - sp[2 * s + 1];
        best = fminf(best, fmaf(dx, dx, dy * dy));
    }

    // Band: d(c,s) < d(c,s*) + 2r + slack.  2r = sqrt(2)/96; slack 1e-4
    // guarantees excluded sites lose even under the reference formula's
    // ~4e-7 d2 rounding noise.
    float thr = sqrtf(best) + 0.01473139f + 1e-4f;
    float thr2 = thr * thr;

    unsigned int entry = 0;
    int cnt = 0;
    for (int s = 0; s < NS; s++) {
        float dx = cx - sp[2 * s];
        float dy = cy - sp[2 * s + 1];
        float d2 = fmaf(dx, dx, dy * dy);
        if (d2 <= thr2) {
            if (cnt < 4) entry |= ((unsigned int)s) << (8 * cnt);
            cnt++;
        }
    }
    if (cnt > 4) {
        entry = (entry & 0xFFu) | 0x0000FE00u | 0x00FF0000u | 0xFF000000u; // fallback
    } else {
        for (int k = cnt; k < 4; k++) entry |= 0xFFu << (8 * k);
    }
    g_grid[cell] = entry;
}

struct SmemTables {
    unsigned int grid[NCELL];
    float4 cand[NS];
    float4 rgb[NS];
};

__device__ __forceinline__ float4 lookup_one(
    float px, float py,
    const unsigned int* __restrict__ sgrid,
    const float4* __restrict__ scand,
    const float4* __restrict__ srgb)
{
    int cx = (int)(px * (float)GR);
    int cy = (int)(py * (float)GR);
    unsigned int e = sgrid[cy * GR + cx];
    int idx = (int)(e & 0xFFu);

    if ((e >> 8) != 0x00FFFFFFu) {
        float a = __fadd_rn(__fmul_rn(px, px), __fmul_rn(py, py));
        float bd = 3.4e38f;
        int bi = 0;
        if (((e >> 8) & 0xFFu) == 0xFEu) {
            for (int s = 0; s < NS; s++) {
                float4 c = scand[s];
                float ee = __fmaf_rn(py, c.y, __fmul_rn(px, c.x));
                float d2 = __fadd_rn(__fsub_rn(a, __fmul_rn(2.0f, ee)), c.z);
                if (d2 < bd) { bd = d2; bi = s; }
            }
        } else {
            #pragma unroll
            for (int k = 0; k < 4; k++) {
                unsigned int cix = (e >> (8 * k)) & 0xFFu;
                if (cix == 0xFFu) break;
                float4 c = scand[cix];
                float ee = __fmaf_rn(py, c.y, __fmul_rn(px, c.x));
                float d2 = __fadd_rn(__fsub_rn(a, __fmul_rn(2.0f, ee)), c.z);
                if (d2 < bd) { bd = d2; bi = (int)cix; }
            }
        }
        idx = bi;
    }
    return srgb[idx];
}

__global__ void __launch_bounds__(256, 5) voronoi_main(
    const float4* __restrict__ x4, float* __restrict__ out, int n)
{
    __shared__ SmemTables st;

    // Vectorized staging: 36 KB grid as uint4 (9 iters/thread), tables by tid<NS.
    {
        const uint4* gg = (const uint4*)g_grid;
        uint4* sg = (uint4*)st.grid;
        #pragma unroll
        for (int i = threadIdx.x; i < NCELL / 4; i += 256) sg[i] = gg[i];
        if (threadIdx.x < NS) {
            st.cand[threadIdx.x] = g_cand[threadIdx.x];
            st.rgb[threadIdx.x]  = g_rgb[threadIdx.x];
        }
    }
    __syncthreads();

    float4* out4 = (float4*)out;
    int tid = blockIdx.x * blockDim.x + threadIdx.x;
    int stride = gridDim.x * blockDim.x;
    int ngroups = n >> 2;   // groups of 4 points

    for (int g = tid; g < ngroups; g += stride) {
        // 4 points = 2 float4 loads
        float4 xa = x4[2 * g + 0];
        float4 xb = x4[2 * g + 1];

        float4 c0 = lookup_one(xa.x, xa.y, st.grid, st.cand, st.rgb);
        float4 c1 = lookup_one(xa.z, xa.w, st.grid, st.cand, st.rgb);
        float4 c2 = lookup_one(xb.x, xb.y, st.grid, st.cand, st.rgb);
        float4 c3 = lookup_one(xb.z, xb.w, st.grid, st.cand, st.rgb);

        out4[3 * g + 0] = make_float4(c0.x, c0.y, c0.z, c1.x);
        out4[3 * g + 1] = make_float4(c1.y, c1.z, c2.x, c2.y);
        out4[3 * g + 2] = make_float4(c2.z, c3.x, c3.y, c3.z);
    }

    // Remainder points (n not divisible by 4) — scalar path.
    int rem_start = ngroups << 2;
    for (int i = rem_start + tid; i < n; i += stride) {
        const float2* x2 = (const float2*)x4;
        float2 pt = x2[i];
        float4 c = lookup_one(pt.x, pt.y, st.grid, st.cand, st.rgb);
        out[3 * i + 0] = c.x;
        out[3 * i + 1] = c.y;
        out[3 * i + 2] = c.z;
    }
}

extern "C" void kernel_launch(void* const* d_in, const int* in_sizes, int n_in,
                              void* d_out, int out_size) {
    const float4* x = (const float4*)d_in[0];
    const float*  p = (const float*)d_in[1];
    float* out = (float*)d_out;
    int n = in_sizes[0] / 2;

    build_lut<<<(NCELL + 255) / 256, 256>>>(p);
    voronoi_main<<<740, 256>>>(x, out, n);
}